// round 5
// baseline (speedup 1.0000x reference)
#include <cuda_runtime.h>
#include <cuda_bf16.h>
#include <math.h>

#define HW 128
#define NPIX (HW*HW)            // 16384
#define NANCH 9
#define NBOX (NPIX*NANCH)       // 147456
#define NSORT 262144            // 2^18, power of two >= NBOX
#define COUT 512
#define IMG_MAX 2048.0f
#define MAX_OUT 300

// ---------------- scratch (static device memory; no allocation) ----------------
__device__ float g_x1[NPIX*COUT];        // conv1 output (post-relu)
__device__ float g_x2[NPIX*COUT];        // conv2 output
__device__ float g_boxes[NBOX*4];        // decoded boxes
__device__ unsigned long long g_sk[NSORT]; // sort keys: (~score_bits)<<32 | idx
__device__ float g_wt[45*512 + 45];      // transposed head weights + bias

// ---------------- conv 3x3 (SAME), CIN -> 512, tiled fp32 GEMM ----------------
// FIRST=true : in = features (param), relu on input, relu on output, writes g_x1.
// FIRST=false: in = g_x1 (device symbol), no relu, writes g_x2.
// NOTE: device globals are referenced ONLY inside device code — passing them as
// kernel args from host passes the host shadow address (silently wrong on GB300/ATS).
template<int CIN, bool FIRST>
__global__ void conv3x3_kernel(const float* __restrict__ in_param,
                               const float* __restrict__ w,
                               const float* __restrict__ bias)
{
    const float* __restrict__ in = FIRST ? in_param : (const float*)g_x1;
    float* __restrict__ out = FIRST ? g_x1 : g_x2;

    const int mt = blockIdx.x;          // 0..255
    const int y  = mt >> 1;
    const int x0 = (mt & 1) << 6;
    const int n0 = blockIdx.y << 7;     // 0,128,256,384
    const int tid = threadIdx.x;
    const int tm = tid >> 4;            // 0..15 (pixel group of 4)
    const int tn = tid & 15;            // 0..15 (channel group of 8)

    __shared__ __align__(16) float As[16][64];
    __shared__ __align__(16) float Bs[16][128];

    float acc[4][8];
#pragma unroll
    for (int i = 0; i < 4; i++)
#pragma unroll
        for (int j = 0; j < 8; j++) acc[i][j] = 0.f;

    const int pa = tid >> 2;            // 0..63 pixel for A-load
    const int qa = tid & 3;             // 0..3  k-quad for A-load

    for (int kh = 0; kh < 3; kh++) {
        const int yy = y + kh - 1;
        if (yy < 0 || yy >= HW) continue;       // uniform across block
        for (int kw = 0; kw < 3; kw++) {
            const float* wbase = w + (size_t)((kh*3 + kw)*CIN) * 512 + n0;
            const int xx = x0 + pa + kw - 1;
            const bool xok = (xx >= 0 && xx < HW);
            const float* arow = in + (size_t)(yy*HW + xx) * CIN;

            for (int c0 = 0; c0 < CIN; c0 += 16) {
                // --- load A tile: 16 k x 64 px ---
                float4 av = make_float4(0.f, 0.f, 0.f, 0.f);
                if (xok) {
                    av = *reinterpret_cast<const float4*>(arow + c0 + qa*4);
                    if (FIRST) {
                        av.x = fmaxf(av.x, 0.f); av.y = fmaxf(av.y, 0.f);
                        av.z = fmaxf(av.z, 0.f); av.w = fmaxf(av.w, 0.f);
                    }
                }
                As[qa*4+0][pa] = av.x;
                As[qa*4+1][pa] = av.y;
                As[qa*4+2][pa] = av.z;
                As[qa*4+3][pa] = av.w;
                // --- load B tile: 16 k x 128 n ---
#pragma unroll
                for (int r = 0; r < 2; r++) {
                    int idx = tid + r*256;
                    int k   = idx >> 5;       // 0..15
                    int n4  = idx & 31;       // 0..31
                    float4 bv = *reinterpret_cast<const float4*>(wbase + (size_t)(c0+k)*512 + n4*4);
                    *reinterpret_cast<float4*>(&Bs[k][n4*4]) = bv;
                }
                __syncthreads();
#pragma unroll
                for (int k = 0; k < 16; k++) {
                    float4 a  = *reinterpret_cast<const float4*>(&As[k][tm*4]);
                    float4 b0 = *reinterpret_cast<const float4*>(&Bs[k][tn*8]);
                    float4 b1 = *reinterpret_cast<const float4*>(&Bs[k][tn*8+4]);
                    float aa[4] = {a.x, a.y, a.z, a.w};
                    float bb[8] = {b0.x, b0.y, b0.z, b0.w, b1.x, b1.y, b1.z, b1.w};
#pragma unroll
                    for (int i = 0; i < 4; i++)
#pragma unroll
                        for (int j = 0; j < 8; j++)
                            acc[i][j] = fmaf(aa[i], bb[j], acc[i][j]);
                }
                __syncthreads();
            }
        }
    }

    // epilogue: bias (+relu for conv1) and store
    float bsv[8];
#pragma unroll
    for (int j = 0; j < 8; j++) bsv[j] = bias[n0 + tn*8 + j];
#pragma unroll
    for (int i = 0; i < 4; i++) {
        float v[8];
#pragma unroll
        for (int j = 0; j < 8; j++) {
            v[j] = acc[i][j] + bsv[j];
            if (FIRST) v[j] = fmaxf(v[j], 0.f);
        }
        float* o = out + (size_t)(y*HW + x0 + tm*4 + i) * 512 + n0 + tn*8;
        *reinterpret_cast<float4*>(o)     = make_float4(v[0], v[1], v[2], v[3]);
        *reinterpret_cast<float4*>(o + 4) = make_float4(v[4], v[5], v[6], v[7]);
    }
}

// ---------------- head weight transpose: wt[o][c], o<9 score else box ----------------
__global__ void prep_wt_kernel(const float* __restrict__ wsc, const float* __restrict__ bsc,
                               const float* __restrict__ wbx, const float* __restrict__ bbx)
{
    int t = blockIdx.x * blockDim.x + threadIdx.x;
    if (t < 45*512) {
        int o = t / 512, c = t % 512;
        g_wt[t] = (o < 9) ? wsc[c*9 + o] : wbx[c*36 + (o-9)];
    }
    if (t < 45) g_wt[45*512 + t] = (t < 9) ? bsc[t] : bbx[t-9];
}

// ---------------- heads (1x1 conv) + sigmoid + decode + keygen ----------------
// Block: 256 threads, 5 pixels. Threads 0..224: (pixel, output o in 0..44).
__global__ void heads_kernel()
{
    __shared__ __align__(16) float xs[5][512];
    __shared__ float ho[5][45];
    const int tid = threadIdx.x;
    const int p0 = blockIdx.x * 5;

    for (int i = tid; i < 5*512; i += 256) {
        int pp = i >> 9, c = i & 511;
        int pg = p0 + pp;
        xs[pp][c] = (pg < NPIX) ? g_x2[(size_t)pg*512 + c] : 0.f;
    }
    __syncthreads();

    if (tid < 225) {
        int pix = tid / 45, o = tid % 45;
        const float* wrow = g_wt + o*512;
        const float* xr = xs[pix];
        float acc = 0.f;
#pragma unroll 4
        for (int c = 0; c < 512; c += 4) {
            float4 x4 = *reinterpret_cast<const float4*>(&xr[c]);
            float4 w4 = *reinterpret_cast<const float4*>(&wrow[c]);
            acc = fmaf(x4.x, w4.x, acc);
            acc = fmaf(x4.y, w4.y, acc);
            acc = fmaf(x4.z, w4.z, acc);
            acc = fmaf(x4.w, w4.w, acc);
        }
        ho[pix][o] = acc + g_wt[45*512 + o];
    }
    __syncthreads();

    if (tid < 45) {
        int pp = tid / 9, a = tid % 9;
        int pg = p0 + pp;
        if (pg < NPIX) {
            float logit = ho[pp][a];
            float sc = 1.f / (1.f + expf(-logit));
            float dy = ho[pp][9 + 4*a + 0];
            float dx = ho[pp][9 + 4*a + 1];
            float dh = ho[pp][9 + 4*a + 2];
            float dw = ho[pp][9 + 4*a + 3];
            int yy = pg >> 7, xx = pg & 127;
            float scale = (a < 3) ? 128.f : ((a < 6) ? 256.f : 512.f);
            int rm = a % 3;
            float ratio = (rm == 0) ? 0.5f : ((rm == 1) ? 1.f : 2.f);
            float sr = sqrtf(ratio);
            float ah = scale * sr, aw = scale / sr;
            float acy = (yy + 0.5f) * 16.f, acx = (xx + 0.5f) * 16.f;
            float cy = acy + dy * ah, cx = acx + dx * aw;
            float h = ah * expf(dh), w = aw * expf(dw);
            float y1 = fminf(fmaxf(cy - 0.5f*h, 0.f), IMG_MAX);
            float x1 = fminf(fmaxf(cx - 0.5f*w, 0.f), IMG_MAX);
            float y2 = fminf(fmaxf(cy + 0.5f*h, 0.f), IMG_MAX);
            float x2 = fminf(fmaxf(cx + 0.5f*w, 0.f), IMG_MAX);
            int idx = pg*9 + a;
            *reinterpret_cast<float4*>(&g_boxes[idx*4]) = make_float4(y1, x1, y2, x2);
            // 64-bit key: ascending sort == descending score; ties -> lower idx first
            g_sk[idx] = ((unsigned long long)(~__float_as_uint(sc)) << 32) | (unsigned)idx;
        }
    }
}

// ---------------- padding for bitonic sort ----------------
__global__ void pad_kernel()
{
    int i = NBOX + blockIdx.x * blockDim.x + threadIdx.x;
    if (i < NSORT) g_sk[i] = ~0ULL;      // decodes to score 0.0 -> never selected
}

// ---------------- bitonic sort (ascending), 64-bit keys ----------------
__global__ void bitonic_global_kernel(int k, int j)
{
    int i = blockIdx.x * blockDim.x + threadIdx.x;
    int l = i ^ j;
    if (l > i) {
        unsigned long long a = g_sk[i];
        unsigned long long b = g_sk[l];
        bool up = ((i & k) == 0);
        if (up ? (a > b) : (a < b)) { g_sk[i] = b; g_sk[l] = a; }
    }
}

// Handles all substages with j <= 1024 for stage k. Block = 1024 threads, 2048 elems.
__global__ void bitonic_fused_kernel(int k, int j0)
{
    __shared__ unsigned long long s[2048];
    const int base = blockIdx.x * 2048;
    const int tid = threadIdx.x;
    s[tid]        = g_sk[base + tid];
    s[tid + 1024] = g_sk[base + tid + 1024];
    __syncthreads();
    for (int j = j0; j >= 1; j >>= 1) {
        int i = 2*tid - (tid & (j - 1));     // pair base index
        int l = i + j;
        unsigned long long a = s[i];
        unsigned long long b = s[l];
        bool up = (((base + i) & k) == 0);
        if (up ? (a > b) : (a < b)) { s[i] = b; s[l] = a; }
        __syncthreads();
    }
    g_sk[base + tid]        = s[tid];
    g_sk[base + tid + 1024] = s[tid + 1024];
}

// ---------------- greedy NMS over sorted candidates (single block) ----------------
__global__ void nms_kernel(float* __restrict__ out, int out_size)
{
    __shared__ float sy1[MAX_OUT], sx1[MAX_OUT], sy2[MAX_OUT], sx2[MAX_OUT], sar[MAX_OUT];
    __shared__ int nsel;
    __shared__ int st;           // 0 = keep, 1 = suppressed, 2 = terminate
    __shared__ float cand[5];    // y1,x1,y2,x2,score
    const int tid = threadIdx.x;

    for (int i = tid; i < out_size; i += blockDim.x) out[i] = 0.f;
    if (tid == 0) nsel = 0;
    __syncthreads();

    for (int i = 0; i < NSORT; i++) {
        if (tid == 0) {
            unsigned long long key = g_sk[i];
            float sc = __uint_as_float(~(unsigned)(key >> 32));
            if (!(sc >= 0.5f)) {
                st = 2;
            } else {
                st = 0;
                unsigned id = (unsigned)(key & 0xFFFFFFFFu);
                float4 b = *reinterpret_cast<const float4*>(&g_boxes[id*4]);
                cand[0] = b.x; cand[1] = b.y; cand[2] = b.z; cand[3] = b.w;
                cand[4] = sc;
            }
        }
        __syncthreads();
        if (st == 2) break;

        float y1 = cand[0], x1 = cand[1], y2 = cand[2], x2 = cand[3];
        float ca = (y2 - y1) * (x2 - x1);
        int m = nsel;
        for (int s = tid; s < m; s += blockDim.x) {
            float iy = fmaxf(0.f, fminf(y2, sy2[s]) - fmaxf(y1, sy1[s]));
            float ix = fmaxf(0.f, fminf(x2, sx2[s]) - fmaxf(x1, sx1[s]));
            float inter = iy * ix;
            float iou = inter / (sar[s] + ca - inter + 1e-9f);
            if (iou > 0.7f) st = 1;
        }
        __syncthreads();
        if (st == 0 && tid == 0) {
            sy1[m] = y1; sx1[m] = x1; sy2[m] = y2; sx2[m] = x2; sar[m] = ca;
            if (m*4 + 3 < out_size) {
                out[m*4 + 0] = y1; out[m*4 + 1] = x1; out[m*4 + 2] = y2; out[m*4 + 3] = x2;
            }
            if (1200 + m < out_size) out[1200 + m] = cand[4];
            if (1500 + m < out_size) out[1500 + m] = 1.f;
            nsel = m + 1;
        }
        __syncthreads();
        if (nsel >= MAX_OUT) break;
    }
}

// ---------------- launch ----------------
extern "C" void kernel_launch(void* const* d_in, const int* in_sizes, int n_in,
                              void* d_out, int out_size)
{
    // Identify inputs BY ELEMENT COUNT (robust to harness input ordering).
    const float *features = 0, *w1 = 0, *b1 = 0, *w2 = 0, *b2 = 0;
    const float *wsc = 0, *bsc = 0, *wbx = 0, *bbx = 0;
    for (int i = 0; i < n_in; i++) {
        int sz = in_sizes[i];
        const float* p = (const float*)d_in[i];
        switch (sz) {
            case 16777216: features = p; break;
            case 4718592:  w1 = p; break;
            case 2359296:  w2 = p; break;
            case 18432:    wbx = p; break;
            case 4608:     wsc = p; break;
            case 36:       bbx = p; break;
            case 9:        bsc = p; break;
            case 512:      if (!b1) b1 = p; else b2 = p; break;
            default: break; // region_limit (1) ignored; fixed at 300
        }
    }
    if (!b2) b2 = b1;
    float* out = (float*)d_out;

    dim3 cgrid(256, 4);
    conv3x3_kernel<1024, true ><<<cgrid, 256>>>(features, w1, b1);
    conv3x3_kernel< 512, false><<<cgrid, 256>>>(nullptr, w2, b2);

    prep_wt_kernel<<<91, 256>>>(wsc, bsc, wbx, bbx);
    heads_kernel<<<(NPIX + 4) / 5, 256>>>();
    pad_kernel<<<(NSORT - NBOX + 255) / 256, 256>>>();

    // bitonic sort of g_sk (ascending)
    for (int k = 2; k <= NSORT; k <<= 1) {
        int j = k >> 1;
        while (j > 1024) {
            bitonic_global_kernel<<<NSORT / 256, 256>>>(k, j);
            j >>= 1;
        }
        bitonic_fused_kernel<<<NSORT / 2048, 1024>>>(k, j);
    }

    nms_kernel<<<1, 256>>>(out, out_size);
}